// round 3
// baseline (speedup 1.0000x reference)
#include <cuda_runtime.h>
#include <cuda_bf16.h>

// ZBL repulsion energy: per-pair 4-term exponential screening, scatter-add to atoms.
// Inputs (metadata order):
//  0: N (scalar)        1: Zf [N] f32      2: rij [P] f32      3: cutoff_values [P] f32
//  4: idx_i [P] i32     5: idx_j [P] i32   6: adiv [1]         7: apow [1]
//  8..11: c1..c4 [1]    12..15: a1..a4 [1]
// Output: f32 [N]

#define NA_MAX 500000
#define PAIRS_PER_THREAD 8

// per-atom (z, Zf) packed: both gathers per atom are one 8B load
__device__ float2 g_zzf[NA_MAX];
// derived scalar params for the pairs kernel:
// [0]=sp(adiv) [1..4]=KEHALF*c_k_normalized [5..8]=sp(a_k)
__device__ float g_par[12];

__device__ __forceinline__ float softplus_accurate(float x) {
    return log1pf(expf(x));
}

// Fused: computes per-atom z table, zeroes out, and (one thread) derives pair params.
__global__ void atoms_kernel(const float* __restrict__ Zf, float* __restrict__ out, int n,
                             const float* __restrict__ adiv, const float* __restrict__ apow,
                             const float* __restrict__ c1, const float* __restrict__ c2,
                             const float* __restrict__ c3, const float* __restrict__ c4,
                             const float* __restrict__ a1, const float* __restrict__ a2,
                             const float* __restrict__ a3, const float* __restrict__ a4) {
    int i = blockIdx.x * blockDim.x + threadIdx.x;
    if (i == 0) {
        const float KEHALF = 7.199822675975274f;
        float c1p = softplus_accurate(c1[0]);
        float c2p = softplus_accurate(c2[0]);
        float c3p = softplus_accurate(c3[0]);
        float c4p = softplus_accurate(c4[0]);
        float inv_csum = KEHALF / (c1p + c2p + c3p + c4p);
        g_par[0] = softplus_accurate(adiv[0]);
        g_par[1] = c1p * inv_csum;
        g_par[2] = c2p * inv_csum;
        g_par[3] = c3p * inv_csum;
        g_par[4] = c4p * inv_csum;
        g_par[5] = softplus_accurate(a1[0]);
        g_par[6] = softplus_accurate(a2[0]);
        g_par[7] = softplus_accurate(a3[0]);
        g_par[8] = softplus_accurate(a4[0]);
    }
    if (i < n) {
        // every thread computes its own sp(apow): broadcast load + ~2 MUFU, cheap,
        // avoids a separate serial prep kernel on the critical path
        float spapow = softplus_accurate(apow[0]);
        float Z = Zf[i];
        float z = exp2f(spapow * __log2f(Z));   // z = Z^sp(apow), Z in [1,94]
        g_zzf[i] = make_float2(z, Z);
        out[i] = 0.0f;                          // d_out is poisoned by the harness
    }
}

__global__ void __launch_bounds__(256) pairs_kernel(
    const float* __restrict__ rij, const float* __restrict__ cv,
    const int* __restrict__ idx_i, const int* __restrict__ idx_j,
    float* __restrict__ out, int npairs) {
    long long base = (long long)(blockIdx.x * blockDim.x + threadIdx.x) * PAIRS_PER_THREAD;
    if (base >= npairs) return;

    const float spadiv = g_par[0];
    const float k1 = g_par[1], k2 = g_par[2], k3 = g_par[3], k4 = g_par[4];
    const float s1 = g_par[5], s2 = g_par[6], s3 = g_par[7], s4 = g_par[8];

    if (base + PAIRS_PER_THREAD <= npairs) {
        // ---- vector fast path: front-batch ALL loads for max MLP ----
        float r[PAIRS_PER_THREAD], c[PAIRS_PER_THREAD];
        int ia[PAIRS_PER_THREAD], ja[PAIRS_PER_THREAD];

        // streaming loads: evict-first, don't pollute L2 (atom table lives there)
        const float4* r4p = reinterpret_cast<const float4*>(rij + base);
        const float4* c4p = reinterpret_cast<const float4*>(cv + base);
        const int4*   i4p = reinterpret_cast<const int4*>(idx_i + base);
        const int4*   j4p = reinterpret_cast<const int4*>(idx_j + base);
#pragma unroll
        for (int v = 0; v < PAIRS_PER_THREAD / 4; v++) {
            float4 r4 = __ldcs(r4p + v);
            float4 c4 = __ldcs(c4p + v);
            int4   i4 = __ldcs(i4p + v);
            int4   j4 = __ldcs(j4p + v);
            r[v*4+0] = r4.x; r[v*4+1] = r4.y; r[v*4+2] = r4.z; r[v*4+3] = r4.w;
            c[v*4+0] = c4.x; c[v*4+1] = c4.y; c[v*4+2] = c4.z; c[v*4+3] = c4.w;
            ia[v*4+0] = i4.x; ia[v*4+1] = i4.y; ia[v*4+2] = i4.z; ia[v*4+3] = i4.w;
            ja[v*4+0] = j4.x; ja[v*4+1] = j4.y; ja[v*4+2] = j4.z; ja[v*4+3] = j4.w;
        }

        // issue all 16 gathers before any dependent math (MLP=16)
        float2 zi[PAIRS_PER_THREAD], zj[PAIRS_PER_THREAD];
#pragma unroll
        for (int k = 0; k < PAIRS_PER_THREAD; k++) zi[k] = g_zzf[ia[k]];
#pragma unroll
        for (int k = 0; k < PAIRS_PER_THREAD; k++) zj[k] = g_zzf[ja[k]];

        float contrib[PAIRS_PER_THREAD];
#pragma unroll
        for (int k = 0; k < PAIRS_PER_THREAD; k++) {
            float a = (zi[k].x + zj[k].x) * spadiv;
            float t = -a * r[k];
            float f = k1 * __expf(s1 * t)
                    + k2 * __expf(s2 * t)
                    + k3 * __expf(s3 * t)
                    + k4 * __expf(s4 * t);
            contrib[k] = __fdividef(f * c[k] * zi[k].y * zj[k].y, r[k]);
        }
#pragma unroll
        for (int k = 0; k < PAIRS_PER_THREAD; k++) {
            atomicAdd(&out[ia[k]], contrib[k]);
        }
    } else {
        // ---- scalar tail ----
        int cnt = (int)(npairs - base);
        for (int k = 0; k < cnt; k++) {
            float rk = rij[base + k];
            float ck = cv[base + k];
            int i = idx_i[base + k];
            int j = idx_j[base + k];
            float2 zi = g_zzf[i];
            float2 zj = g_zzf[j];
            float a = (zi.x + zj.x) * spadiv;
            float t = -a * rk;
            float f = k1 * __expf(s1 * t)
                    + k2 * __expf(s2 * t)
                    + k3 * __expf(s3 * t)
                    + k4 * __expf(s4 * t);
            atomicAdd(&out[i], __fdividef(f * ck * zi.y * zj.y, rk));
        }
    }
}

extern "C" void kernel_launch(void* const* d_in, const int* in_sizes, int n_in,
                              void* d_out, int out_size) {
    const float* Zf    = (const float*)d_in[1];
    const float* rij   = (const float*)d_in[2];
    const float* cvv   = (const float*)d_in[3];
    const int*   idx_i = (const int*)d_in[4];
    const int*   idx_j = (const int*)d_in[5];
    const float* adiv  = (const float*)d_in[6];
    const float* apow  = (const float*)d_in[7];
    const float* c1    = (const float*)d_in[8];
    const float* c2    = (const float*)d_in[9];
    const float* c3    = (const float*)d_in[10];
    const float* c4    = (const float*)d_in[11];
    const float* a1    = (const float*)d_in[12];
    const float* a2    = (const float*)d_in[13];
    const float* a3    = (const float*)d_in[14];
    const float* a4    = (const float*)d_in[15];

    int n = in_sizes[1];
    int p = in_sizes[2];
    float* out = (float*)d_out;

    int ab = (n + 255) / 256;
    atoms_kernel<<<ab, 256>>>(Zf, out, n, adiv, apow, c1, c2, c3, c4, a1, a2, a3, a4);

    long long nthreads = ((long long)p + PAIRS_PER_THREAD - 1) / PAIRS_PER_THREAD;
    int pb = (int)((nthreads + 255) / 256);
    pairs_kernel<<<pb, 256>>>(rij, cvv, idx_i, idx_j, out, p);
}

// round 4
// speedup vs baseline: 1.0694x; 1.0694x over previous
#include <cuda_runtime.h>
#include <cuda_bf16.h>

// ZBL repulsion energy: per-pair 4-term exponential screening, scatter-add to atoms.
// Inputs (metadata order):
//  0: N (scalar)        1: Zf [N] f32      2: rij [P] f32      3: cutoff_values [P] f32
//  4: idx_i [P] i32     5: idx_j [P] i32   6: adiv [1]         7: apow [1]
//  8..11: c1..c4 [1]    12..15: a1..a4 [1]
// Output: f32 [N]

#define NA_MAX 500000
#define PPT 4  // pairs per thread

// per-atom Z as uint8 (Z in [1,94]) -> 0.5MB table, ~45% L1-resident for gathers
__device__ unsigned char g_z8[NA_MAX];
// derived scalars: [0]=sp(adiv) [1..4]=KEHALF*c_norm [5..8]=-log2(e)*sp(a_k) [9]=sp(apow)
__device__ float g_par[12];

__device__ __forceinline__ float softplus_accurate(float x) {
    return log1pf(expf(x));
}

// Fused prep: u8 Z table + zero out + (thread 0) derived pair params.
__global__ void atoms_kernel(const float* __restrict__ Zf, float* __restrict__ out, int n,
                             const float* __restrict__ adiv, const float* __restrict__ apow,
                             const float* __restrict__ c1, const float* __restrict__ c2,
                             const float* __restrict__ c3, const float* __restrict__ c4,
                             const float* __restrict__ a1, const float* __restrict__ a2,
                             const float* __restrict__ a3, const float* __restrict__ a4) {
    int i = blockIdx.x * blockDim.x + threadIdx.x;
    if (i == 0) {
        const float KEHALF = 7.199822675975274f;
        const float NLOG2E = -1.4426950408889634f;
        float c1p = softplus_accurate(c1[0]);
        float c2p = softplus_accurate(c2[0]);
        float c3p = softplus_accurate(c3[0]);
        float c4p = softplus_accurate(c4[0]);
        float inv_csum = KEHALF / (c1p + c2p + c3p + c4p);
        g_par[0] = softplus_accurate(adiv[0]);
        g_par[1] = c1p * inv_csum;
        g_par[2] = c2p * inv_csum;
        g_par[3] = c3p * inv_csum;
        g_par[4] = c4p * inv_csum;
        g_par[5] = NLOG2E * softplus_accurate(a1[0]);
        g_par[6] = NLOG2E * softplus_accurate(a2[0]);
        g_par[7] = NLOG2E * softplus_accurate(a3[0]);
        g_par[8] = NLOG2E * softplus_accurate(a4[0]);
        g_par[9] = softplus_accurate(apow[0]);
    }
    if (i < n) {
        g_z8[i] = (unsigned char)__float2int_rn(Zf[i]);
        out[i] = 0.0f;  // d_out is poisoned by the harness
    }
}

__global__ void __launch_bounds__(256) pairs_kernel(
    const float* __restrict__ rij, const float* __restrict__ cv,
    const int* __restrict__ idx_i, const int* __restrict__ idx_j,
    float* __restrict__ out, int npairs) {
    long long base = (long long)(blockIdx.x * blockDim.x + threadIdx.x) * PPT;
    if (base >= npairs) return;

    const float spadiv = g_par[0];
    const float k1 = g_par[1], k2 = g_par[2], k3 = g_par[3], k4 = g_par[4];
    const float q1 = g_par[5], q2 = g_par[6], q3 = g_par[7], q4 = g_par[8];
    const float spapow = g_par[9];

    if (base + PPT <= npairs) {
        // vector loads for the 4 streaming arrays
        float4 r4 = *reinterpret_cast<const float4*>(rij + base);
        float4 c4 = *reinterpret_cast<const float4*>(cv + base);
        int4   i4 = *reinterpret_cast<const int4*>(idx_i + base);
        int4   j4 = *reinterpret_cast<const int4*>(idx_j + base);
        float r[PPT] = {r4.x, r4.y, r4.z, r4.w};
        float c[PPT] = {c4.x, c4.y, c4.z, c4.w};
        int ia[PPT] = {i4.x, i4.y, i4.z, i4.w};
        int ja[PPT] = {j4.x, j4.y, j4.z, j4.w};

        // issue the 8 u8 gathers together (moderate MLP, low spread penalty)
        unsigned char zbi[PPT], zbj[PPT];
#pragma unroll
        for (int k = 0; k < PPT; k++) zbi[k] = g_z8[ia[k]];
#pragma unroll
        for (int k = 0; k < PPT; k++) zbj[k] = g_z8[ja[k]];

        float contrib[PPT];
#pragma unroll
        for (int k = 0; k < PPT; k++) {
            float Zi = (float)zbi[k];
            float Zj = (float)zbj[k];
            // z = Z^sp(apow) via MUFU lg2/ex2 (pipe is nearly idle)
            float zi = exp2f(spapow * __log2f(Zi));
            float zj = exp2f(spapow * __log2f(Zj));
            float u = (zi + zj) * spadiv * r[k];   // a * r
            float f = k1 * exp2f(q1 * u)
                    + k2 * exp2f(q2 * u)
                    + k3 * exp2f(q3 * u)
                    + k4 * exp2f(q4 * u);
            contrib[k] = __fdividef(f * c[k] * Zi * Zj, r[k]);
        }
#pragma unroll
        for (int k = 0; k < PPT; k++) {
            atomicAdd(&out[ia[k]], contrib[k]);
        }
    } else {
        int cnt = (int)(npairs - base);
        for (int k = 0; k < cnt; k++) {
            float rk = rij[base + k];
            float ck = cv[base + k];
            int i = idx_i[base + k];
            int j = idx_j[base + k];
            float Zi = (float)g_z8[i];
            float Zj = (float)g_z8[j];
            float zi = exp2f(spapow * __log2f(Zi));
            float zj = exp2f(spapow * __log2f(Zj));
            float u = (zi + zj) * spadiv * rk;
            float f = k1 * exp2f(q1 * u)
                    + k2 * exp2f(q2 * u)
                    + k3 * exp2f(q3 * u)
                    + k4 * exp2f(q4 * u);
            atomicAdd(&out[i], __fdividef(f * ck * Zi * Zj, rk));
        }
    }
}

extern "C" void kernel_launch(void* const* d_in, const int* in_sizes, int n_in,
                              void* d_out, int out_size) {
    const float* Zf    = (const float*)d_in[1];
    const float* rij   = (const float*)d_in[2];
    const float* cvv   = (const float*)d_in[3];
    const int*   idx_i = (const int*)d_in[4];
    const int*   idx_j = (const int*)d_in[5];
    const float* adiv  = (const float*)d_in[6];
    const float* apow  = (const float*)d_in[7];
    const float* c1    = (const float*)d_in[8];
    const float* c2    = (const float*)d_in[9];
    const float* c3    = (const float*)d_in[10];
    const float* c4    = (const float*)d_in[11];
    const float* a1    = (const float*)d_in[12];
    const float* a2    = (const float*)d_in[13];
    const float* a3    = (const float*)d_in[14];
    const float* a4    = (const float*)d_in[15];

    int n = in_sizes[1];
    int p = in_sizes[2];
    float* out = (float*)d_out;

    int ab = (n + 255) / 256;
    atoms_kernel<<<ab, 256>>>(Zf, out, n, adiv, apow, c1, c2, c3, c4, a1, a2, a3, a4);

    long long nthreads = ((long long)p + PPT - 1) / PPT;
    int pb = (int)((nthreads + 255) / 256);
    pairs_kernel<<<pb, 256>>>(rij, cvv, idx_i, idx_j, out, p);
}

// round 6
// speedup vs baseline: 1.1081x; 1.0362x over previous
#include <cuda_runtime.h>
#include <cuda_bf16.h>

// ZBL repulsion energy: per-pair 4-term exponential screening, scatter-add to atoms.
// Inputs (metadata order):
//  0: N (scalar)        1: Zf [N] f32      2: rij [P] f32      3: cutoff_values [P] f32
//  4: idx_i [P] i32     5: idx_j [P] i32   6: adiv [1]         7: apow [1]
//  8..11: c1..c4 [1]    12..15: a1..a4 [1]
// Output: f32 [N]

#define NA_MAX 500000
#define PPT 4  // pairs per thread

// per-atom Z as uint8 (Z in [1,94]) -> 0.5MB table; with evict-first streaming
// loads this mostly stays L1-resident for the gathers
__device__ unsigned char g_z8[NA_MAX];
// derived scalars: [0]=sp(adiv) [1..4]=KEHALF*c_norm [5..8]=-log2(e)*sp(a_k) [9]=sp(apow)
__device__ float g_par[12];

__device__ __forceinline__ float softplus_accurate(float x) {
    return log1pf(expf(x));
}

// Fused prep: u8 Z table + zero out + (thread 0) derived pair params.
// Vectorized 4 atoms/thread.
__global__ void atoms_kernel(const float* __restrict__ Zf, float* __restrict__ out, int n,
                             const float* __restrict__ adiv, const float* __restrict__ apow,
                             const float* __restrict__ c1, const float* __restrict__ c2,
                             const float* __restrict__ c3, const float* __restrict__ c4,
                             const float* __restrict__ a1, const float* __restrict__ a2,
                             const float* __restrict__ a3, const float* __restrict__ a4) {
    int t = blockIdx.x * blockDim.x + threadIdx.x;
    if (t == 0) {
        const float KEHALF = 7.199822675975274f;
        const float NLOG2E = -1.4426950408889634f;
        float c1p = softplus_accurate(c1[0]);
        float c2p = softplus_accurate(c2[0]);
        float c3p = softplus_accurate(c3[0]);
        float c4p = softplus_accurate(c4[0]);
        float inv_csum = KEHALF / (c1p + c2p + c3p + c4p);
        g_par[0] = softplus_accurate(adiv[0]);
        g_par[1] = c1p * inv_csum;
        g_par[2] = c2p * inv_csum;
        g_par[3] = c3p * inv_csum;
        g_par[4] = c4p * inv_csum;
        g_par[5] = NLOG2E * softplus_accurate(a1[0]);
        g_par[6] = NLOG2E * softplus_accurate(a2[0]);
        g_par[7] = NLOG2E * softplus_accurate(a3[0]);
        g_par[8] = NLOG2E * softplus_accurate(a4[0]);
        g_par[9] = softplus_accurate(apow[0]);
    }
    int base = t * 4;
    if (base + 4 <= n) {
        float4 z4 = *reinterpret_cast<const float4*>(Zf + base);
        uchar4 u;
        u.x = (unsigned char)__float2int_rn(z4.x);
        u.y = (unsigned char)__float2int_rn(z4.y);
        u.z = (unsigned char)__float2int_rn(z4.z);
        u.w = (unsigned char)__float2int_rn(z4.w);
        *reinterpret_cast<uchar4*>(g_z8 + base) = u;
        *reinterpret_cast<float4*>(out + base) = make_float4(0.f, 0.f, 0.f, 0.f);
    } else {
        for (int i = base; i < n; i++) {
            g_z8[i] = (unsigned char)__float2int_rn(Zf[i]);
            out[i] = 0.0f;
        }
    }
}

__global__ void __launch_bounds__(256) pairs_kernel(
    const float* __restrict__ rij, const float* __restrict__ cv,
    const int* __restrict__ idx_i, const int* __restrict__ idx_j,
    float* __restrict__ out, int npairs) {
    long long base = (long long)(blockIdx.x * blockDim.x + threadIdx.x) * PPT;
    if (base >= npairs) return;

    const float spadiv = g_par[0];
    const float k1 = g_par[1], k2 = g_par[2], k3 = g_par[3], k4 = g_par[4];
    const float q1 = g_par[5], q2 = g_par[6], q3 = g_par[7], q4 = g_par[8];
    const float spapow = g_par[9];

    if (base + PPT <= npairs) {
        // streaming loads: evict-first so the 0.5MB atom table stays in L1
        float4 r4 = __ldcs(reinterpret_cast<const float4*>(rij + base));
        float4 c4 = __ldcs(reinterpret_cast<const float4*>(cv + base));
        int4   i4 = __ldcs(reinterpret_cast<const int4*>(idx_i + base));
        int4   j4 = __ldcs(reinterpret_cast<const int4*>(idx_j + base));
        float r[PPT] = {r4.x, r4.y, r4.z, r4.w};
        float c[PPT] = {c4.x, c4.y, c4.z, c4.w};
        int ia[PPT] = {i4.x, i4.y, i4.z, i4.w};
        int ja[PPT] = {j4.x, j4.y, j4.z, j4.w};

        // 8 u8 gathers, read-only path
        unsigned char zbi[PPT], zbj[PPT];
#pragma unroll
        for (int k = 0; k < PPT; k++) zbi[k] = __ldg(&g_z8[ia[k]]);
#pragma unroll
        for (int k = 0; k < PPT; k++) zbj[k] = __ldg(&g_z8[ja[k]]);

        float contrib[PPT];
#pragma unroll
        for (int k = 0; k < PPT; k++) {
            float Zi = (float)zbi[k];
            float Zj = (float)zbj[k];
            // z = Z^sp(apow) via MUFU lg2/ex2 (pipe nearly idle)
            float zi = exp2f(spapow * __log2f(Zi));
            float zj = exp2f(spapow * __log2f(Zj));
            float u = (zi + zj) * spadiv * r[k];   // a * r
            float f = k1 * exp2f(q1 * u)
                    + k2 * exp2f(q2 * u)
                    + k3 * exp2f(q3 * u)
                    + k4 * exp2f(q4 * u);
            contrib[k] = __fdividef(f * c[k] * Zi * Zj, r[k]);
        }
#pragma unroll
        for (int k = 0; k < PPT; k++) {
            atomicAdd(&out[ia[k]], contrib[k]);
        }
    } else {
        int cnt = (int)(npairs - base);
        for (int k = 0; k < cnt; k++) {
            float rk = rij[base + k];
            float ck = cv[base + k];
            int i = idx_i[base + k];
            int j = idx_j[base + k];
            float Zi = (float)g_z8[i];
            float Zj = (float)g_z8[j];
            float zi = exp2f(spapow * __log2f(Zi));
            float zj = exp2f(spapow * __log2f(Zj));
            float u = (zi + zj) * spadiv * rk;
            float f = k1 * exp2f(q1 * u)
                    + k2 * exp2f(q2 * u)
                    + k3 * exp2f(q3 * u)
                    + k4 * exp2f(q4 * u);
            atomicAdd(&out[i], __fdividef(f * ck * Zi * Zj, rk));
        }
    }
}

extern "C" void kernel_launch(void* const* d_in, const int* in_sizes, int n_in,
                              void* d_out, int out_size) {
    const float* Zf    = (const float*)d_in[1];
    const float* rij   = (const float*)d_in[2];
    const float* cvv   = (const float*)d_in[3];
    const int*   idx_i = (const int*)d_in[4];
    const int*   idx_j = (const int*)d_in[5];
    const float* adiv  = (const float*)d_in[6];
    const float* apow  = (const float*)d_in[7];
    const float* c1    = (const float*)d_in[8];
    const float* c2    = (const float*)d_in[9];
    const float* c3    = (const float*)d_in[10];
    const float* c4    = (const float*)d_in[11];
    const float* a1    = (const float*)d_in[12];
    const float* a2    = (const float*)d_in[13];
    const float* a3    = (const float*)d_in[14];
    const float* a4    = (const float*)d_in[15];

    int n = in_sizes[1];
    int p = in_sizes[2];
    float* out = (float*)d_out;

    int athreads = (n + 3) / 4;
    int ab = (athreads + 255) / 256;
    atoms_kernel<<<ab, 256>>>(Zf, out, n, adiv, apow, c1, c2, c3, c4, a1, a2, a3, a4);

    long long nthreads = ((long long)p + PPT - 1) / PPT;
    int pb = (int)((nthreads + 255) / 256);
    pairs_kernel<<<pb, 256>>>(rij, cvv, idx_i, idx_j, out, p);
}